// round 6
// baseline (speedup 1.0000x reference)
#include <cuda_runtime.h>
#include <cuda_bf16.h>
#include <cstdint>
#include <math.h>

#define DIM   4096
#define NH    32
#define HD    128
#define BSZ   2
#define SEQ   2048

// ---------------- scratch (__device__ globals; no allocs allowed) ----------
__device__ float g_q[BSZ*SEQ*DIM];
__device__ float g_k[BSZ*SEQ*DIM];
__device__ float g_v[BSZ*SEQ*DIM];
__device__ float g_cos[SEQ*(HD/2)];
__device__ float g_sin[SEQ*(HD/2)];

// bf16 split buffers (hi/lo)
__device__ __nv_bfloat16 g_xhi[DIM*DIM],  g_xlo[DIM*DIM];
__device__ __nv_bfloat16 g_wqhi[DIM*DIM], g_wqlo[DIM*DIM];
__device__ __nv_bfloat16 g_wkhi[DIM*DIM], g_wklo[DIM*DIM];
__device__ __nv_bfloat16 g_wvhi[DIM*DIM], g_wvlo[DIM*DIM];
__device__ __nv_bfloat16 g_wohi[DIM*DIM], g_wolo[DIM*DIM];
__device__ __nv_bfloat16 g_ahi[DIM*DIM],  g_alo[DIM*DIM];

// ---------------- base-ISA helpers (compute_103-safe) ----------------------
__device__ __forceinline__ uint32_t smem_u32(const void* p) {
    uint32_t a;
    asm("{ .reg .u64 t; cvta.to.shared.u64 t, %1; cvt.u32.u64 %0, t; }" : "=r"(a) : "l"(p));
    return a;
}
__device__ __forceinline__ void cpa16(uint32_t saddr, const void* g) {
    asm volatile("cp.async.cg.shared.global [%0], [%1], 16;" :: "r"(saddr), "l"(g));
}
__device__ __forceinline__ void ldsm4(uint32_t* r, uint32_t addr) {
    asm volatile("ldmatrix.sync.aligned.m8n8.x4.shared.b16 {%0,%1,%2,%3}, [%4];"
        : "=r"(r[0]), "=r"(r[1]), "=r"(r[2]), "=r"(r[3]) : "r"(addr));
}
__device__ __forceinline__ void mma16816(float* c, const uint32_t* a,
                                         uint32_t b0, uint32_t b1) {
    asm volatile("mma.sync.aligned.m16n8k16.row.col.f32.bf16.bf16.f32 "
        "{%0,%1,%2,%3}, {%4,%5,%6,%7}, {%8,%9}, {%0,%1,%2,%3};"
        : "+f"(c[0]), "+f"(c[1]), "+f"(c[2]), "+f"(c[3])
        : "r"(a[0]), "r"(a[1]), "r"(a[2]), "r"(a[3]), "r"(b0), "r"(b1));
}
__device__ __forceinline__ void mma_tf32(float* c, const uint32_t* a,
                                         uint32_t b0, uint32_t b1) {
    asm volatile("mma.sync.aligned.m16n8k8.row.col.f32.tf32.tf32.f32 "
        "{%0,%1,%2,%3}, {%4,%5,%6,%7}, {%8,%9}, {%0,%1,%2,%3};"
        : "+f"(c[0]), "+f"(c[1]), "+f"(c[2]), "+f"(c[3])
        : "r"(a[0]), "r"(a[1]), "r"(a[2]), "r"(a[3]), "r"(b0), "r"(b1));
}
__device__ __forceinline__ uint32_t to_tf32(float x) {
    uint32_t r;
    asm("cvt.rna.tf32.f32 %0, %1;" : "=r"(r) : "f"(x));
    return r;
}
__device__ __forceinline__ uint32_t sw128(uint32_t off) {
    return off ^ ((off >> 3) & 0x70);
}

// ---------------------------------------------------------------------------
// fp32 -> (bf16 hi, bf16 lo) split, vectorized
// ---------------------------------------------------------------------------
__global__ void split_bf16(const float* __restrict__ in,
                           __nv_bfloat16* __restrict__ hi,
                           __nv_bfloat16* __restrict__ lo, int n4)
{
    int i = blockIdx.x * 256 + threadIdx.x;
    if (i >= n4) return;
    float4 v = ((const float4*)in)[i];
    __nv_bfloat162 h01 = __floats2bfloat162_rn(v.x, v.y);
    __nv_bfloat162 h23 = __floats2bfloat162_rn(v.z, v.w);
    float2 f01 = __bfloat1622float2(h01);
    float2 f23 = __bfloat1622float2(h23);
    __nv_bfloat162 l01 = __floats2bfloat162_rn(v.x - f01.x, v.y - f01.y);
    __nv_bfloat162 l23 = __floats2bfloat162_rn(v.z - f23.x, v.w - f23.y);
    ((__nv_bfloat162*)hi)[2*i]   = h01;
    ((__nv_bfloat162*)hi)[2*i+1] = h23;
    ((__nv_bfloat162*)lo)[2*i]   = l01;
    ((__nv_bfloat162*)lo)[2*i+1] = l23;
}

// ---------------------------------------------------------------------------
// Split-bf16 tensor-core GEMM (NT): C[m,n]=sum_k A[m,k]*W[n,k], 4096^3.
// CTA 128x128, 4 warps (2Mx2N), warp tile 64x64, BK=64 (SW128 128B rows),
// 3-stage cp.async pipeline. 6 mma per ldsm.x4.
// ---------------------------------------------------------------------------
__global__ void __launch_bounds__(128, 1)
gemm_mma(const __nv_bfloat16* __restrict__ Ahi, const __nv_bfloat16* __restrict__ Alo,
         const __nv_bfloat16* __restrict__ Bhi, const __nv_bfloat16* __restrict__ Blo,
         float* __restrict__ C)
{
    extern __shared__ char sm[];
    const uint32_t s0 = smem_u32(sm);

    const int tid  = threadIdx.x;
    const int wid  = tid >> 5;
    const int lane = tid & 31;
    const int bx = blockIdx.x;
    const int by = blockIdx.y;
    const int warp_m = wid >> 1;   // 0..1 (64 rows each)
    const int warp_n = wid & 1;    // 0..1 (64 cols each)

    float acc[4][8][4];
#pragma unroll
    for (int t = 0; t < 4; t++)
#pragma unroll
        for (int n = 0; n < 8; n++)
#pragma unroll
            for (int j = 0; j < 4; j++) acc[t][n][j] = 0.0f;

    const __nv_bfloat16* gp[4] = {Ahi, Alo, Bhi, Blo};

    // stage: 64KB = 4 mats x 16KB; mat = 128 rows x 128B (64 bf16), SW128
    auto load_stage = [&](int kt, int stage) {
        uint32_t sbase = s0 + stage * 65536;
#pragma unroll
        for (int m = 0; m < 4; m++) {
            const int rowbase = (m < 2 ? by : bx) * 128;
            const __nv_bfloat16* G = gp[m];
#pragma unroll
            for (int i = 0; i < 8; i++) {
                int li = tid + i * 128;           // 0..1023
                int r = li >> 3, c = li & 7;      // row, 16B chunk
                const void* g = G + (size_t)(rowbase + r) * 4096 + kt * 64 + c * 8;
                cpa16(sbase + m * 16384 + sw128((uint32_t)(r * 128 + c * 16)), g);
            }
        }
        asm volatile("cp.async.commit_group;" ::: "memory");
    };

    const int lrow  = (lane & 7) + ((lane >> 3) & 1) * 8;
    const int khalf = (lane >> 4) * 16;

    const int NT = 4096 / 64;   // 64 k-tiles

    load_stage(0, 0);
    load_stage(1, 1);

    for (int kt = 0; kt < NT; kt++) {
        if (kt < NT - 1) asm volatile("cp.async.wait_group 1;" ::: "memory");
        else             asm volatile("cp.async.wait_group 0;" ::: "memory");
        __syncthreads();

        const uint32_t sbase = s0 + (kt % 3) * 65536;
        if (kt + 2 < NT) load_stage(kt + 2, (kt + 2) % 3);

#pragma unroll
        for (int s = 0; s < 4; s++) {
            uint32_t ah[4][4], al[4][4], bh[4][4], bl[4][4];
#pragma unroll
            for (int t = 0; t < 4; t++) {
                uint32_t off = sw128((uint32_t)((warp_m * 64 + t * 16 + lrow) * 128
                                                + khalf + s * 32));
                ldsm4(ah[t], sbase + off);
                ldsm4(al[t], sbase + 16384 + off);
            }
#pragma unroll
            for (int u = 0; u < 4; u++) {
                uint32_t off = sw128((uint32_t)((warp_n * 64 + u * 16 + lrow) * 128
                                                + khalf + s * 32));
                ldsm4(bh[u], sbase + 32768 + off);
                ldsm4(bl[u], sbase + 49152 + off);
            }
#pragma unroll
            for (int t = 0; t < 4; t++)
#pragma unroll
                for (int u = 0; u < 4; u++)
#pragma unroll
                    for (int j = 0; j < 2; j++) {
                        float* c = acc[t][u * 2 + j];
                        mma16816(c, ah[t], bh[u][j], bh[u][j + 2]);
                        mma16816(c, ah[t], bl[u][j], bl[u][j + 2]);
                        mma16816(c, al[t], bh[u][j], bh[u][j + 2]);
                    }
        }
    }

    const int g  = lane >> 2;
    const int qc = lane & 3;
#pragma unroll
    for (int t = 0; t < 4; t++) {
        const int row = by * 128 + warp_m * 64 + t * 16 + g;
#pragma unroll
        for (int n = 0; n < 8; n++) {
            const int col = bx * 128 + warp_n * 64 + n * 8 + qc * 2;
            *(float2*)&C[(size_t)row * 4096 + col] =
                make_float2(acc[t][n][0], acc[t][n][1]);
            *(float2*)&C[(size_t)(row + 8) * 4096 + col] =
                make_float2(acc[t][n][2], acc[t][n][3]);
        }
    }
}

// ---------------------------------------------------------------------------
// RoPE
// ---------------------------------------------------------------------------
__global__ void rope_table(float* ct, float* st)
{
    int idx = blockIdx.x * 256 + threadIdx.x;
    if (idx >= SEQ * (HD / 2)) return;
    int s = idx >> 6;
    int j = idx & 63;
    double inv = pow(10000.0, -(double)(2 * j) / 128.0);
    double a = (double)s * inv;
    ct[idx] = (float)cos(a);
    st[idx] = (float)sin(a);
}

__global__ void rope_apply(float* __restrict__ q, float* __restrict__ k,
                           const float* __restrict__ ct, const float* __restrict__ st)
{
    int idx = blockIdx.x * 256 + threadIdx.x;
    if (idx >= BSZ * SEQ * NH * (HD / 2)) return;
    int j = idx & 63;
    int h = (idx >> 6) & 31;
    int s = (idx >> 11) & 2047;
    int b = idx >> 22;
    size_t base = (((size_t)(b * SEQ + s) * NH + h) << 7) + 2 * j;
    float c  = ct[s * 64 + j];
    float sn = st[s * 64 + j];
    float2 xq = *(float2*)&q[base];
    float2 xk = *(float2*)&k[base];
    float2 oq, ok;
    oq.x = xq.x * c - xq.y * sn;
    oq.y = xq.x * sn + xq.y * c;
    ok.x = xk.x * c - xk.y * sn;
    ok.y = xk.x * sn + xk.y * c;
    *(float2*)&q[base] = oq;
    *(float2*)&k[base] = ok;
}

// ---------------------------------------------------------------------------
// Tensor-core causal flash attention (tf32 mma.m16n8k8).
// Epilogue now writes bf16 hi/lo split directly (feeds wo GEMM).
// ---------------------------------------------------------------------------
#define KS_STRIDE 132
#define PS_STRIDE 68
#define ATTN_SMEM ((2*64*KS_STRIDE + 4*16*PS_STRIDE) * 4)

__global__ void __launch_bounds__(128)
attn_tc(const float* __restrict__ Q, const float* __restrict__ Kg,
        const float* __restrict__ Vg,
        __nv_bfloat16* __restrict__ Ohi, __nv_bfloat16* __restrict__ Olo)
{
    extern __shared__ float smf[];
    float* Ks = smf;
    float* Vs = smf + 64 * KS_STRIDE;
    float* Ps = smf + 2 * 64 * KS_STRIDE;

    const int tid  = threadIdx.x;
    const int w    = tid >> 5;
    const int lane = tid & 31;
    const int qt = blockIdx.x;
    const int h  = blockIdx.y;
    const int b  = blockIdx.z;
    const int g  = lane >> 2;
    const int qc = lane & 3;
    float* Pw = Ps + w * 16 * PS_STRIDE;

    const float scale = 0.08838834764831845f;
    const int q0 = qt * 64 + w * 16;

    uint32_t qa[16][4];
    {
        const float* q_r0 = Q + ((size_t)b * SEQ + q0 + g)     * 4096 + h * 128;
        const float* q_r1 = Q + ((size_t)b * SEQ + q0 + g + 8) * 4096 + h * 128;
#pragma unroll
        for (int kc = 0; kc < 16; kc++) {
            qa[kc][0] = to_tf32(q_r0[kc * 8 + qc]     * scale);
            qa[kc][1] = to_tf32(q_r1[kc * 8 + qc]     * scale);
            qa[kc][2] = to_tf32(q_r0[kc * 8 + qc + 4] * scale);
            qa[kc][3] = to_tf32(q_r1[kc * 8 + qc + 4] * scale);
        }
    }

    float o[16][4];
#pragma unroll
    for (int n = 0; n < 16; n++)
#pragma unroll
        for (int j = 0; j < 4; j++) o[n][j] = 0.0f;
    float m0 = -1e30f, m1 = -1e30f, l0 = 0.0f, l1 = 0.0f;

    for (int kt = 0; kt <= qt; kt++) {
        if (kt) __syncthreads();
#pragma unroll
        for (int i = 0; i < 16; i++) {
            int li = tid + i * 128;
            int row = li >> 5, c4 = li & 31;
            size_t gsrc = ((size_t)b * SEQ + kt * 64 + row) * 4096 + h * 128 + c4 * 4;
            float4 kv = *(const float4*)&Kg[gsrc];
            float4 vv = *(const float4*)&Vg[gsrc];
            uint4 kb = make_uint4(to_tf32(kv.x), to_tf32(kv.y), to_tf32(kv.z), to_tf32(kv.w));
            uint4 vb = make_uint4(to_tf32(vv.x), to_tf32(vv.y), to_tf32(vv.z), to_tf32(vv.w));
            *(uint4*)&Ks[row * KS_STRIDE + c4 * 4] = kb;
            *(uint4*)&Vs[row * KS_STRIDE + c4 * 4] = vb;
        }
        __syncthreads();

        float sreg[8][4];
#pragma unroll
        for (int j = 0; j < 8; j++) {
            sreg[j][0] = sreg[j][1] = sreg[j][2] = sreg[j][3] = 0.0f;
            const uint32_t* krow = (const uint32_t*)&Ks[(j * 8 + g) * KS_STRIDE];
#pragma unroll
            for (int kc = 0; kc < 16; kc++)
                mma_tf32(sreg[j], qa[kc], krow[kc * 8 + qc], krow[kc * 8 + qc + 4]);
        }

        if (kt == qt) {
            const int kb = kt * 64;
#pragma unroll
            for (int j = 0; j < 8; j++) {
                int key0 = kb + j * 8 + 2 * qc;
                if (key0     > q0 + g)     sreg[j][0] = -1e30f;
                if (key0 + 1 > q0 + g)     sreg[j][1] = -1e30f;
                if (key0     > q0 + g + 8) sreg[j][2] = -1e30f;
                if (key0 + 1 > q0 + g + 8) sreg[j][3] = -1e30f;
            }
        }

        float mx0 = -1e30f, mx1 = -1e30f;
#pragma unroll
        for (int j = 0; j < 8; j++) {
            mx0 = fmaxf(mx0, fmaxf(sreg[j][0], sreg[j][1]));
            mx1 = fmaxf(mx1, fmaxf(sreg[j][2], sreg[j][3]));
        }
        mx0 = fmaxf(mx0, __shfl_xor_sync(0xffffffffu, mx0, 1));
        mx0 = fmaxf(mx0, __shfl_xor_sync(0xffffffffu, mx0, 2));
        mx1 = fmaxf(mx1, __shfl_xor_sync(0xffffffffu, mx1, 1));
        mx1 = fmaxf(mx1, __shfl_xor_sync(0xffffffffu, mx1, 2));
        float mn0 = fmaxf(m0, mx0), mn1 = fmaxf(m1, mx1);
        float f0 = __expf(m0 - mn0), f1 = __expf(m1 - mn1);
        m0 = mn0; m1 = mn1;

        float sum0 = 0.0f, sum1 = 0.0f;
        uint32_t* PwU = (uint32_t*)Pw;
#pragma unroll
        for (int j = 0; j < 8; j++) {
            float p0 = __expf(sreg[j][0] - mn0);
            float p1 = __expf(sreg[j][1] - mn0);
            float p2 = __expf(sreg[j][2] - mn1);
            float p3 = __expf(sreg[j][3] - mn1);
            sum0 += p0 + p1;
            sum1 += p2 + p3;
            PwU[g * PS_STRIDE       + j * 8 + 2 * qc]     = to_tf32(p0);
            PwU[g * PS_STRIDE       + j * 8 + 2 * qc + 1] = to_tf32(p1);
            PwU[(g + 8) * PS_STRIDE + j * 8 + 2 * qc]     = to_tf32(p2);
            PwU[(g + 8) * PS_STRIDE + j * 8 + 2 * qc + 1] = to_tf32(p3);
        }
        sum0 += __shfl_xor_sync(0xffffffffu, sum0, 1);
        sum0 += __shfl_xor_sync(0xffffffffu, sum0, 2);
        sum1 += __shfl_xor_sync(0xffffffffu, sum1, 1);
        sum1 += __shfl_xor_sync(0xffffffffu, sum1, 2);
        l0 = l0 * f0 + sum0;
        l1 = l1 * f1 + sum1;

#pragma unroll
        for (int n = 0; n < 16; n++) {
            o[n][0] *= f0; o[n][1] *= f0;
            o[n][2] *= f1; o[n][3] *= f1;
        }
        __syncwarp();

        uint32_t pa[8][4];
#pragma unroll
        for (int kc = 0; kc < 8; kc++) {
            pa[kc][0] = PwU[g * PS_STRIDE       + kc * 8 + qc];
            pa[kc][1] = PwU[(g + 8) * PS_STRIDE + kc * 8 + qc];
            pa[kc][2] = PwU[g * PS_STRIDE       + kc * 8 + qc + 4];
            pa[kc][3] = PwU[(g + 8) * PS_STRIDE + kc * 8 + qc + 4];
        }

#pragma unroll
        for (int n = 0; n < 16; n++) {
#pragma unroll
            for (int kc = 0; kc < 8; kc++) {
                uint32_t b0 = ((const uint32_t*)Vs)[(kc * 8 + qc)     * KS_STRIDE + n * 8 + g];
                uint32_t b1 = ((const uint32_t*)Vs)[(kc * 8 + qc + 4) * KS_STRIDE + n * 8 + g];
                mma_tf32(o[n], pa[kc], b0, b1);
            }
        }
    }

    // epilogue: normalize and emit bf16 hi/lo split directly
    const float inv0 = 1.0f / l0;
    const float inv1 = 1.0f / l1;
    const size_t base0 = ((size_t)b * SEQ + q0 + g)     * 4096 + h * 128;
    const size_t base1 = ((size_t)b * SEQ + q0 + g + 8) * 4096 + h * 128;
#pragma unroll
    for (int n = 0; n < 16; n++) {
        float v00 = o[n][0] * inv0, v01 = o[n][1] * inv0;
        float v10 = o[n][2] * inv1, v11 = o[n][3] * inv1;
        __nv_bfloat162 h0 = __floats2bfloat162_rn(v00, v01);
        __nv_bfloat162 h1 = __floats2bfloat162_rn(v10, v11);
        float2 r0 = __bfloat1622float2(h0);
        float2 r1 = __bfloat1622float2(h1);
        __nv_bfloat162 lo0 = __floats2bfloat162_rn(v00 - r0.x, v01 - r0.y);
        __nv_bfloat162 lo1 = __floats2bfloat162_rn(v10 - r1.x, v11 - r1.y);
        *(__nv_bfloat162*)&Ohi[base0 + n * 8 + 2 * qc] = h0;
        *(__nv_bfloat162*)&Olo[base0 + n * 8 + 2 * qc] = lo0;
        *(__nv_bfloat162*)&Ohi[base1 + n * 8 + 2 * qc] = h1;
        *(__nv_bfloat162*)&Olo[base1 + n * 8 + 2 * qc] = lo1;
    }
}

// ---------------------------------------------------------------------------
extern "C" void kernel_launch(void* const* d_in, const int* in_sizes, int n_in,
                              void* d_out, int out_size)
{
    const float* x = (const float*)d_in[0];
    int off = (n_in >= 6 && in_sizes[1] <= 4) ? 2 : 1;
    const float* wq = (const float*)d_in[off + 0];
    const float* wk = (const float*)d_in[off + 1];
    const float* wv = (const float*)d_in[off + 2];
    const float* wo = (const float*)d_in[off + 3];
    float* out = (float*)d_out;

    float *q, *k, *v, *ct, *st;
    cudaGetSymbolAddress((void**)&q,  g_q);
    cudaGetSymbolAddress((void**)&k,  g_k);
    cudaGetSymbolAddress((void**)&v,  g_v);
    cudaGetSymbolAddress((void**)&ct, g_cos);
    cudaGetSymbolAddress((void**)&st, g_sin);

    __nv_bfloat16 *xhi, *xlo, *wqhi, *wqlo, *wkhi, *wklo, *wvhi, *wvlo, *wohi, *wolo, *ahi, *alo;
    cudaGetSymbolAddress((void**)&xhi,  g_xhi);   cudaGetSymbolAddress((void**)&xlo,  g_xlo);
    cudaGetSymbolAddress((void**)&wqhi, g_wqhi);  cudaGetSymbolAddress((void**)&wqlo, g_wqlo);
    cudaGetSymbolAddress((void**)&wkhi, g_wkhi);  cudaGetSymbolAddress((void**)&wklo, g_wklo);
    cudaGetSymbolAddress((void**)&wvhi, g_wvhi);  cudaGetSymbolAddress((void**)&wvlo, g_wvlo);
    cudaGetSymbolAddress((void**)&wohi, g_wohi);  cudaGetSymbolAddress((void**)&wolo, g_wolo);
    cudaGetSymbolAddress((void**)&ahi,  g_ahi);   cudaGetSymbolAddress((void**)&alo,  g_alo);

    cudaFuncSetAttribute(gemm_mma, cudaFuncAttributeMaxDynamicSharedMemorySize, 196608);
    cudaFuncSetAttribute(attn_tc,  cudaFuncAttributeMaxDynamicSharedMemorySize, ATTN_SMEM);

    const int n4 = DIM * DIM / 4;
    const int cgrid = (n4 + 255) / 256;
    dim3 gg(DIM / 128, DIM / 128);

    // ordering chosen so launches 5-7 are gemm_mma (ncu -s 5 lands on a GEMM)
    split_bf16<<<cgrid, 256>>>(x,  xhi, xlo, n4);
    split_bf16<<<cgrid, 256>>>(wq, wqhi, wqlo, n4);
    split_bf16<<<cgrid, 256>>>(wk, wkhi, wklo, n4);
    split_bf16<<<cgrid, 256>>>(wv, wvhi, wvlo, n4);
    split_bf16<<<cgrid, 256>>>(wo, wohi, wolo, n4);

    gemm_mma<<<gg, 128, 196608>>>(xhi, xlo, wqhi, wqlo, q);
    gemm_mma<<<gg, 128, 196608>>>(xhi, xlo, wkhi, wklo, k);
    gemm_mma<<<gg, 128, 196608>>>(xhi, xlo, wvhi, wvlo, v);

    rope_table<<<(SEQ * (HD / 2) + 255) / 256, 256>>>(ct, st);
    rope_apply<<<(BSZ * SEQ * NH * (HD / 2) + 255) / 256, 256>>>(q, k, ct, st);

    attn_tc<<<dim3(SEQ / 64, NH, BSZ), 128, ATTN_SMEM>>>(q, k, v, ahi, alo);

    gemm_mma<<<gg, 128, 196608>>>(ahi, alo, wohi, wolo, out);
}